// round 16
// baseline (speedup 1.0000x reference)
#include <cuda_runtime.h>
#include <cuda_fp16.h>
#include <cstdint>

#define BATCH 4
#define CHAN  12
#define CPAIR (CHAN/2)
#define HGRID 16
#define WGRID 16
#define DGRID 8
#define IMH   1024
#define IMW   1024

// ---------------------------------------------------------------------------
// One block per output row (b,i). 4096 blocks x 256 threads, 4 px/thread.
// R13/R15 showed ~36.6us regardless of occ/ILP trade with no pipe saturated
// -> issue+latency mixed limit. This round cuts instruction count ~28% at
// constant byte volume:
//   - LDS.64 loads 2 half2 words (4 channels) per slot: gather instrs halve,
//     wavefronts unchanged. Banks: word pair {(6d+16h+2p)%32, +1}; 8 d-values
//     give 8 disjoint bank pairs, h parity shifts +16 into a disjoint set.
//     All addrs 8B-aligned (24|8, 192|8).
//   - depth-lerp in fp16 (HSUB2+HFMA2) BEFORE cvt: converts halve, FFMA -40%.
//     Adds ~1 fp16 rounding -> rel_err ~3-4e-4 (< 1e-3 gate).
//   - h-blend fp32 lerp; guide LDG.128; 12x STG.128.
// dh == dl+1 always (guide in [0,1)). grid-H <- j, grid-W <- i.
// ---------------------------------------------------------------------------

__device__ __forceinline__ uint2 lds_u64(uint32_t addr) {
    uint2 v;
    asm("ld.shared.v2.u32 {%0,%1}, [%2];" : "=r"(v.x), "=r"(v.y) : "r"(addr));
    return v;
}

__device__ __forceinline__ __half2 u2h2(uint32_t u) {
    return *reinterpret_cast<__half2*>(&u);
}

__global__ void __launch_bounds__(256) slice_kernel(
    const float* __restrict__ grid,
    const float* __restrict__ guide,
    float* __restrict__ out)
{
    __shared__ __half2 cellH[HGRID * DGRID * CPAIR];   // 768 words = 3 KB

    const int row = blockIdx.x;          // 0 .. B*IMH-1
    const int b   = row >> 10;
    const int i   = row & (IMH - 1);
    const int tid = threadIdx.x;

    // --- per-row W interpolation factors (uniform across block) ---
    float wwc = (float)i * (1.0f / (float)(IMH - 1)) * (float)(WGRID - 1);
    float w0f = floorf(wwc);
    int   w0  = (int)w0f;
    int   w1  = min(w0 + 1, WGRID - 1);
    float fw  = wwc - w0f;
    float fwl = 1.0f - fw;

    // --- stage cellH: 768 half2 words, 3 per thread ---
    // grid layout: [b][c][h][w][d] -> offset (((b*12+c)*16+h)*16 + w)*8 + d
    {
        const float* gb = grid + (size_t)b * (CHAN * HGRID * WGRID * DGRID);
        #pragma unroll
        for (int idx = tid; idx < HGRID * DGRID * CPAIR; idx += 256) {
            int c2  = idx / (HGRID * DGRID);
            int rem = idx - c2 * (HGRID * DGRID);
            int h   = rem >> 3;
            int d   = rem & 7;
            int c0  = 2 * c2;
            const float* p0 = gb + ((size_t)c0 * HGRID + h) * (WGRID * DGRID) + d;
            const float* p1 = p0 + (size_t)HGRID * WGRID * DGRID;   // channel c0+1
            float v0 = fwl * p0[w0 * DGRID] + fw * p0[w1 * DGRID];
            float v1 = fwl * p1[w0 * DGRID] + fw * p1[w1 * DGRID];
            cellH[(h * DGRID + d) * CPAIR + c2] = __floats2half2_rn(v0, v1);
        }
    }
    __syncthreads();

    uint32_t sbase;
    {
        asm("{ .reg .u64 t; cvta.to.shared.u64 t, %1; cvt.u32.u64 %0, t; }"
            : "=r"(sbase) : "l"(cellH));
    }

    const float* grow = guide + (size_t)row * IMW;
    float* orow = out + (size_t)b * (CHAN * IMH * IMW) + (size_t)i * IMW;
    const size_t cs = (size_t)IMH * IMW;

    const int j0 = tid * 4;

    // --- guide: one vectorized load for 4 consecutive pixels ---
    float4 g4 = *reinterpret_cast<const float4*>(grow + j0);
    float gk[4] = {g4.x, g4.y, g4.z, g4.w};

    // --- precompute per-pixel slot addresses + weights ---
    uint32_t a00[4], a10[4];
    __half2  dwh[4];
    float    fhv[4];
    #pragma unroll
    for (int k = 0; k < 4; k++) {
        int j = j0 + k;

        // depth: guide in [0,1) -> dc in [0,7) -> dl in [0,6], dh = dl+1
        float dc = gk[k] * (float)(DGRID - 1);
        float dlo_f = floorf(dc);
        int   dl = (int)dlo_f;
        float dw = dc - dlo_f;
        dwh[k] = __float2half2_rn(dw);

        // grid-H from j
        float hhc = (float)j * (1.0f / (float)(IMW - 1)) * (float)(HGRID - 1);
        float h0f = floorf(hhc);
        int   h0  = (int)h0f;
        int   h1  = min(h0 + 1, HGRID - 1);
        fhv[k] = hhc - h0f;

        a00[k] = sbase + (uint32_t)(h0 * 192 + dl * 24);
        a10[k] = sbase + (uint32_t)(h1 * 192 + dl * 24);
    }

    // --- gather + blend: 3 channel-pair iterations, 4 channels each ---
    #pragma unroll
    for (int p = 0; p < 3; p++) {
        uint32_t off = (uint32_t)(p * 8);
        float ch0[4], ch1[4], ch2[4], ch3[4];
        #pragma unroll
        for (int k = 0; k < 4; k++) {
            // load 4 slots x 4 channels (2 half2 words each)
            uint2 lo0 = lds_u64(a00[k] + off);        // h0, d_lo
            uint2 hi0 = lds_u64(a00[k] + 24 + off);   // h0, d_hi
            uint2 lo1 = lds_u64(a10[k] + off);        // h1, d_lo
            uint2 hi1 = lds_u64(a10[k] + 24 + off);   // h1, d_hi

            // depth lerp in fp16: r = lo + dw*(hi - lo)
            __half2 dwk = dwh[k];
            __half2 r0a = __hfma2(dwk, __hsub2(u2h2(hi0.x), u2h2(lo0.x)), u2h2(lo0.x));
            __half2 r0b = __hfma2(dwk, __hsub2(u2h2(hi0.y), u2h2(lo0.y)), u2h2(lo0.y));
            __half2 r1a = __hfma2(dwk, __hsub2(u2h2(hi1.x), u2h2(lo1.x)), u2h2(lo1.x));
            __half2 r1b = __hfma2(dwk, __hsub2(u2h2(hi1.y), u2h2(lo1.y)), u2h2(lo1.y));

            // convert to fp32
            float2 f0a = __half22float2(r0a);
            float2 f0b = __half22float2(r0b);
            float2 f1a = __half22float2(r1a);
            float2 f1b = __half22float2(r1b);

            // h blend in fp32: v = f0 + fh*(f1 - f0)
            float fh = fhv[k];
            ch0[k] = fmaf(fh, f1a.x - f0a.x, f0a.x);
            ch1[k] = fmaf(fh, f1a.y - f0a.y, f0a.y);
            ch2[k] = fmaf(fh, f1b.x - f0b.x, f0b.x);
            ch3[k] = fmaf(fh, f1b.y - f0b.y, f0b.y);
        }
        int c = 4 * p;
        *reinterpret_cast<float4*>(orow + (size_t)(c + 0) * cs + j0) =
            make_float4(ch0[0], ch0[1], ch0[2], ch0[3]);
        *reinterpret_cast<float4*>(orow + (size_t)(c + 1) * cs + j0) =
            make_float4(ch1[0], ch1[1], ch1[2], ch1[3]);
        *reinterpret_cast<float4*>(orow + (size_t)(c + 2) * cs + j0) =
            make_float4(ch2[0], ch2[1], ch2[2], ch2[3]);
        *reinterpret_cast<float4*>(orow + (size_t)(c + 3) * cs + j0) =
            make_float4(ch3[0], ch3[1], ch3[2], ch3[3]);
    }
}

extern "C" void kernel_launch(void* const* d_in, const int* in_sizes, int n_in,
                              void* d_out, int out_size) {
    const float* grid  = (const float*)d_in[0];  // (4,12,16,16,8)
    const float* guide = (const float*)d_in[1];  // (4,1,1024,1024)
    // d_in[2] = input_image: reference uses only its shape; never read.
    float* out = (float*)d_out;                  // (4,12,1024,1024)

    slice_kernel<<<BATCH * IMH, 256>>>(grid, guide, out);
}